// round 9
// baseline (speedup 1.0000x reference)
#include <cuda_runtime.h>
#include <cuda_bf16.h>
#include <math_constants.h>
#include <stdint.h>

// Problem constants
#define BATCH   96
#define NW      10
#define NTOK    144            // window tokens
#define CDIM    192
#define HEADS   6
#define DH      32
#define MTOT    (BATCH*NW*NTOK)        // 138240
#define NHEADTOT (BATCH*NW*HEADS)      // 5760
#define NN2     (NTOK*NTOK)            // 20736
#define BIASTOT (NW*HEADS*NN2)         // 1244160
#define QKVN    (3*CDIM)               // 576
#define SCALE   0.17677669529663687f   // 32^-0.5

// -------- scratch (device globals; no runtime allocation allowed) ----------
__device__ float g_q[NHEADTOT * NTOK * DH];   // [head][n][d], pre-scaled
__device__ float g_k[NHEADTOT * NTOK * DH];
__device__ float g_v[NHEADTOT * NTOK * DH];
__device__ float g_att[MTOT * CDIM];          // attention output, [B,nW,N,C]
__device__ float g_bias[BIASTOT];             // [w][h][i*N+j]

// ---------------------------------------------------------------------------
// K0: materialize relative-position bias
// ---------------------------------------------------------------------------
__global__ void build_bias_kernel(const float* __restrict__ bias_table,
                                  const int* __restrict__ pidx) {
    int idx = blockIdx.x * blockDim.x + threadIdx.x;
    if (idx >= BIASTOT) return;
    int wh = idx / NN2;
    int ij = idx - wh * NN2;
    g_bias[idx] = bias_table[pidx[ij] * (NW * HEADS) + wh];
}

// ---------------------------------------------------------------------------
// SGEMM 8x8 microtile. BM=256, BN=64, BK=16, 256 threads.
// tx=tid&7 -> cols tx*8..+7; ty=tid>>3 (0..31) -> rows ty*8..+7.
// ---------------------------------------------------------------------------
#define SBM 256
#define SBN 64
#define SBK 16

// ---------------- K1: QKV GEMM + scatter to g_q/g_k/g_v -------------------
__global__ __launch_bounds__(256)
void qkv8_kernel(const float* __restrict__ X,
                 const float* __restrict__ W,
                 const float* __restrict__ bqkv) {
    __shared__ float As[SBK][SBM];   // 16 KB
    __shared__ float Bs[SBK][SBN];   // 4 KB

    const int tid = threadIdx.x;
    const int tx  = tid & 7;
    const int ty  = tid >> 3;
    const int m0  = blockIdx.x * SBM;
    const int n0  = blockIdx.y * SBN;

    float acc[8][8];
    #pragma unroll
    for (int i = 0; i < 8; ++i)
        #pragma unroll
        for (int j = 0; j < 8; ++j) acc[i][j] = 0.f;

    for (int k0 = 0; k0 < CDIM; k0 += SBK) {
        // A tile: 256 rows x 16 k = 1024 float4; 4 per thread (transpose store)
        #pragma unroll
        for (int l = 0; l < 4; ++l) {
            int idx = tid + l * 256;
            int row = idx >> 2;
            int c4  = idx & 3;
            float4 a = *(const float4*)(X + (size_t)(m0 + row) * CDIM + k0 + c4 * 4);
            As[c4 * 4 + 0][row] = a.x;
            As[c4 * 4 + 1][row] = a.y;
            As[c4 * 4 + 2][row] = a.z;
            As[c4 * 4 + 3][row] = a.w;
        }
        // B tile: 16 k x 64 n = 256 float4; 1 per thread
        {
            int krow = tid >> 4;
            int c4   = tid & 15;
            *(float4*)&Bs[krow][c4 * 4] =
                *(const float4*)(W + (size_t)(k0 + krow) * QKVN + n0 + c4 * 4);
        }
        __syncthreads();

        #pragma unroll
        for (int k = 0; k < SBK; ++k) {
            float a[8], b[8];
            *(float4*)&a[0] = *(const float4*)&As[k][ty * 8];
            *(float4*)&a[4] = *(const float4*)&As[k][ty * 8 + 4];
            *(float4*)&b[0] = *(const float4*)&Bs[k][tx * 8];
            *(float4*)&b[4] = *(const float4*)&Bs[k][tx * 8 + 4];
            #pragma unroll
            for (int i = 0; i < 8; ++i)
                #pragma unroll
                for (int j = 0; j < 8; ++j)
                    acc[i][j] = fmaf(a[i], b[j], acc[i][j]);
        }
        __syncthreads();
    }

    // epilogue: 8-col group lies in one q/k/v type and one head (8 | 32 | 192)
    const int cg = n0 + tx * 8;
    float bq[8];
    *(float4*)&bq[0] = *(const float4*)(bqkv + cg);
    *(float4*)&bq[4] = *(const float4*)(bqkv + cg + 4);

    const int tt  = cg / CDIM;          // 0=q,1=k,2=v
    const int rem = cg - tt * CDIM;
    const int h   = rem >> 5;
    const int d   = rem & 31;           // 0,8,16,24
    float* dstbase = (tt == 0) ? g_q : (tt == 1) ? g_k : g_v;
    const float sc = (tt == 0) ? SCALE : 1.0f;

    #pragma unroll
    for (int i = 0; i < 8; ++i) {
        int m  = m0 + ty * 8 + i;
        int bw = m / NTOK;
        int nn = m - bw * NTOK;
        float* dst = dstbase + (size_t)((bw * HEADS + h) * NTOK + nn) * DH + d;
        float4 v0, v1;
        v0.x = (acc[i][0] + bq[0]) * sc; v0.y = (acc[i][1] + bq[1]) * sc;
        v0.z = (acc[i][2] + bq[2]) * sc; v0.w = (acc[i][3] + bq[3]) * sc;
        v1.x = (acc[i][4] + bq[4]) * sc; v1.y = (acc[i][5] + bq[5]) * sc;
        v1.z = (acc[i][6] + bq[6]) * sc; v1.w = (acc[i][7] + bq[7]) * sc;
        *(float4*)(dst)     = v0;
        *(float4*)(dst + 4) = v1;
    }
}

// ---------------- K3: projection GEMM -> d_out -----------------------------
__global__ __launch_bounds__(256)
void proj8_kernel(const float* __restrict__ Wp,
                  const float* __restrict__ bp,
                  float* __restrict__ out) {
    __shared__ float As[SBK][SBM];
    __shared__ float Bs[SBK][SBN];

    const int tid = threadIdx.x;
    const int tx  = tid & 7;
    const int ty  = tid >> 3;
    const int m0  = blockIdx.x * SBM;
    const int n0  = blockIdx.y * SBN;

    float acc[8][8];
    #pragma unroll
    for (int i = 0; i < 8; ++i)
        #pragma unroll
        for (int j = 0; j < 8; ++j) acc[i][j] = 0.f;

    for (int k0 = 0; k0 < CDIM; k0 += SBK) {
        #pragma unroll
        for (int l = 0; l < 4; ++l) {
            int idx = tid + l * 256;
            int row = idx >> 2;
            int c4  = idx & 3;
            float4 a = *(const float4*)(g_att + (size_t)(m0 + row) * CDIM + k0 + c4 * 4);
            As[c4 * 4 + 0][row] = a.x;
            As[c4 * 4 + 1][row] = a.y;
            As[c4 * 4 + 2][row] = a.z;
            As[c4 * 4 + 3][row] = a.w;
        }
        {
            int krow = tid >> 4;
            int c4   = tid & 15;
            *(float4*)&Bs[krow][c4 * 4] =
                *(const float4*)(Wp + (size_t)(k0 + krow) * CDIM + n0 + c4 * 4);
        }
        __syncthreads();

        #pragma unroll
        for (int k = 0; k < SBK; ++k) {
            float a[8], b[8];
            *(float4*)&a[0] = *(const float4*)&As[k][ty * 8];
            *(float4*)&a[4] = *(const float4*)&As[k][ty * 8 + 4];
            *(float4*)&b[0] = *(const float4*)&Bs[k][tx * 8];
            *(float4*)&b[4] = *(const float4*)&Bs[k][tx * 8 + 4];
            #pragma unroll
            for (int i = 0; i < 8; ++i)
                #pragma unroll
                for (int j = 0; j < 8; ++j)
                    acc[i][j] = fmaf(a[i], b[j], acc[i][j]);
        }
        __syncthreads();
    }

    const int cg = n0 + tx * 8;
    float bq[8];
    *(float4*)&bq[0] = *(const float4*)(bp + cg);
    *(float4*)&bq[4] = *(const float4*)(bp + cg + 4);

    #pragma unroll
    for (int i = 0; i < 8; ++i) {
        int m = m0 + ty * 8 + i;
        float* dst = out + (size_t)m * CDIM + cg;
        float4 v0, v1;
        v0.x = acc[i][0] + bq[0]; v0.y = acc[i][1] + bq[1];
        v0.z = acc[i][2] + bq[2]; v0.w = acc[i][3] + bq[3];
        v1.x = acc[i][4] + bq[4]; v1.y = acc[i][5] + bq[5];
        v1.z = acc[i][6] + bq[6]; v1.w = acc[i][7] + bq[7];
        *(float4*)(dst)     = v0;
        *(float4*)(dst + 4) = v1;
    }
}

// ---------------------------------------------------------------------------
// K2: fused attention, one block per (b,w,h) head. (R1 known-good version)
// ---------------------------------------------------------------------------
__global__ __launch_bounds__(160)
void attn_kernel(const float* __restrict__ mask) {
    __shared__ float Ks[NTOK * DH];        // 18432 B
    __shared__ float Vs[NTOK * DH];        // 18432 B
    __shared__ float BMs[NTOK * 17];       // 9792 B

    const int head = blockIdx.x;
    const int h    = head % HEADS;
    const int bw   = head / HEADS;
    const int b    = head / (NW * HEADS);
    const int t    = threadIdx.x;

    const float* kb = g_k + (size_t)head * NTOK * DH;
    const float* vb = g_v + (size_t)head * NTOK * DH;
    const float* qb = g_q + (size_t)head * NTOK * DH;
    const float* biasWH = g_bias + (size_t)(head % (NW * HEADS)) * NN2;
    const float* maskB  = mask + (size_t)b * NN2;

    for (int idx = t; idx < NTOK * DH / 4; idx += 160) {
        ((float4*)Ks)[idx] = ((const float4*)kb)[idx];
        ((float4*)Vs)[idx] = ((const float4*)vb)[idx];
    }

    float q[DH];
    if (t < NTOK) {
        const float4* qr = (const float4*)(qb + t * DH);
        #pragma unroll
        for (int d4 = 0; d4 < 8; ++d4) {
            float4 v4 = qr[d4];
            q[d4 * 4 + 0] = v4.x; q[d4 * 4 + 1] = v4.y;
            q[d4 * 4 + 2] = v4.z; q[d4 * 4 + 3] = v4.w;
        }
    }

    float o[DH];
    #pragma unroll
    for (int d = 0; d < DH; ++d) o[d] = 0.f;
    float mrun = -CUDART_INF_F;
    float srun = 0.f;

    for (int jt = 0; jt < 9; ++jt) {       // 9 tiles of 16 keys
        __syncthreads();                   // also covers initial K/V load
        for (int idx = t; idx < 576; idx += 160) {
            int row = idx >> 2;
            int c4  = idx & 3;
            int gi  = row * NTOK + jt * 16 + c4 * 4;
            float4 bb = *(const float4*)(biasWH + gi);
            float4 mm = *(const float4*)(maskB + gi);
            float* dst = &BMs[row * 17 + c4 * 4];
            dst[0] = bb.x + mm.x; dst[1] = bb.y + mm.y;
            dst[2] = bb.z + mm.z; dst[3] = bb.w + mm.w;
        }
        __syncthreads();

        if (t < NTOK) {
            float st[16];
            float tmax = -CUDART_INF_F;
            #pragma unroll
            for (int jj = 0; jj < 16; ++jj) {
                const int j = jt * 16 + jj;
                const float4* kr = (const float4*)(Ks + j * DH);
                float a0 = 0.f, a1 = 0.f, a2 = 0.f, a3 = 0.f;
                #pragma unroll
                for (int d4 = 0; d4 < 8; ++d4) {
                    float4 kv = kr[d4];                  // broadcast LDS
                    a0 = fmaf(q[d4 * 4 + 0], kv.x, a0);
                    a1 = fmaf(q[d4 * 4 + 1], kv.y, a1);
                    a2 = fmaf(q[d4 * 4 + 2], kv.z, a2);
                    a3 = fmaf(q[d4 * 4 + 3], kv.w, a3);
                }
                st[jj] = (a0 + a1) + (a2 + a3) + BMs[t * 17 + jj];
                tmax = fmaxf(tmax, st[jj]);
            }
            const float mnew = fmaxf(mrun, tmax);
            const float corr = __expf(mrun - mnew);      // 0 on first tile
            srun *= corr;
            #pragma unroll
            for (int d = 0; d < DH; ++d) o[d] *= corr;
            #pragma unroll
            for (int jj = 0; jj < 16; ++jj) {
                const float p = __expf(st[jj] - mnew);
                srun += p;
                const float4* vr = (const float4*)(Vs + (jt * 16 + jj) * DH);
                #pragma unroll
                for (int d4 = 0; d4 < 8; ++d4) {
                    float4 vv = vr[d4];                  // broadcast LDS
                    o[d4 * 4 + 0] = fmaf(p, vv.x, o[d4 * 4 + 0]);
                    o[d4 * 4 + 1] = fmaf(p, vv.y, o[d4 * 4 + 1]);
                    o[d4 * 4 + 2] = fmaf(p, vv.z, o[d4 * 4 + 2]);
                    o[d4 * 4 + 3] = fmaf(p, vv.w, o[d4 * 4 + 3]);
                }
            }
            mrun = mnew;
        }
    }

    if (t < NTOK) {
        const float inv = 1.0f / srun;
        float* op = g_att + ((size_t)bw * NTOK + t) * CDIM + h * DH;
        #pragma unroll
        for (int d4 = 0; d4 < 8; ++d4) {
            float4 v4;
            v4.x = o[d4 * 4 + 0] * inv; v4.y = o[d4 * 4 + 1] * inv;
            v4.z = o[d4 * 4 + 2] * inv; v4.w = o[d4 * 4 + 3] * inv;
            *(float4*)(op + d4 * 4) = v4;
        }
    }
}

// ---------------------------------------------------------------------------
extern "C" void kernel_launch(void* const* d_in, const int* in_sizes, int n_in,
                              void* d_out, int out_size) {
    const float* x          = (const float*)d_in[0];
    const float* mask       = (const float*)d_in[1];
    const float* w_qkv      = (const float*)d_in[2];
    const float* b_qkv      = (const float*)d_in[3];
    const float* w_proj     = (const float*)d_in[4];
    const float* b_proj     = (const float*)d_in[5];
    const float* bias_table = (const float*)d_in[6];
    const int*   pidx       = (const int*)d_in[7];
    float* out = (float*)d_out;

    build_bias_kernel<<<(BIASTOT + 255) / 256, 256>>>(bias_table, pidx);
    qkv8_kernel<<<dim3(MTOT / SBM, QKVN / SBN), 256>>>(x, w_qkv, b_qkv);
    attn_kernel<<<NHEADTOT, 160>>>(mask);
    proj8_kernel<<<dim3(MTOT / SBM, CDIM / SBN), 256>>>(w_proj, b_proj, out);
}

// round 10
// speedup vs baseline: 1.4466x; 1.4466x over previous
#include <cuda_runtime.h>
#include <cuda_bf16.h>
#include <math_constants.h>
#include <stdint.h>

// Problem constants
#define BATCH   96
#define NW      10
#define NTOK    144            // window tokens
#define CDIM    192
#define HEADS   6
#define DH      32
#define MTOT    (BATCH*NW*NTOK)        // 138240
#define NHEADTOT (BATCH*NW*HEADS)      // 5760
#define NN2     (NTOK*NTOK)            // 20736
#define BIASTOT (NW*HEADS*NN2)         // 1244160
#define QKVN    (3*CDIM)               // 576
#define SCALE   0.17677669529663687f   // 32^-0.5

// ---------------- packed f32x2 helpers (for proj kernel) -------------------
__device__ __forceinline__ unsigned long long pack2(float lo, float hi) {
    unsigned long long r;
    asm("mov.b64 %0, {%1, %2};" : "=l"(r) : "f"(lo), "f"(hi));
    return r;
}
__device__ __forceinline__ float2 unpack2(unsigned long long v) {
    float2 f;
    asm("mov.b64 {%0, %1}, %2;" : "=f"(f.x), "=f"(f.y) : "l"(v));
    return f;
}
__device__ __forceinline__ unsigned long long fma2(unsigned long long a,
                                                   unsigned long long b,
                                                   unsigned long long c) {
    unsigned long long d;
    asm("fma.rn.f32x2 %0, %1, %2, %3;" : "=l"(d) : "l"(a), "l"(b), "l"(c));
    return d;
}
__device__ __forceinline__ unsigned long long d_as_ull(double x) {
    return __double_as_longlong(x);
}

// -------- scratch (device globals; no runtime allocation allowed) ----------
__device__ float g_q[NHEADTOT * NTOK * DH];   // [head][n][d], pre-scaled
__device__ float g_k[NHEADTOT * NTOK * DH];
__device__ float g_v[NHEADTOT * NTOK * DH];
__device__ float g_att[MTOT * CDIM];          // attention output, [B,nW,N,C]
__device__ float g_bias[BIASTOT];             // [w][h][i*N+j]

// ---------------------------------------------------------------------------
// K0: materialize relative-position bias
// ---------------------------------------------------------------------------
__global__ void build_bias_kernel(const float* __restrict__ bias_table,
                                  const int* __restrict__ pidx) {
    int idx = blockIdx.x * blockDim.x + threadIdx.x;
    if (idx >= BIASTOT) return;
    int wh = idx / NN2;
    int ij = idx - wh * NN2;
    g_bias[idx] = bias_table[pidx[ij] * (NW * HEADS) + wh];
}

// ---------------------------------------------------------------------------
// K1: QKV GEMM (R1 verbatim, at fp32 roofline)
// ---------------------------------------------------------------------------
#define GBM 128
#define GBN 64
#define GBK 16

__global__ __launch_bounds__(256)
void qkv_gemm_kernel(const float* __restrict__ X,
                     const float* __restrict__ W,
                     const float* __restrict__ bqkv) {
    __shared__ float As[GBK][GBM];
    __shared__ float Bs[GBK][GBN];

    const int m0 = blockIdx.x * GBM;
    const int n0 = blockIdx.y * GBN;
    const int tid = threadIdx.x;
    const int tx = tid & 15;
    const int ty = tid >> 4;

    float acc[8][4];
    #pragma unroll
    for (int r = 0; r < 8; ++r)
        #pragma unroll
        for (int c = 0; c < 4; ++c) acc[r][c] = 0.f;

    for (int k0 = 0; k0 < CDIM; k0 += GBK) {
        #pragma unroll
        for (int l = 0; l < 2; ++l) {
            int idx = tid + l * 256;
            int row = idx >> 2;
            int c4  = idx & 3;
            float4 a = *(const float4*)(X + (size_t)(m0 + row) * CDIM + k0 + c4 * 4);
            As[c4 * 4 + 0][row] = a.x;
            As[c4 * 4 + 1][row] = a.y;
            As[c4 * 4 + 2][row] = a.z;
            As[c4 * 4 + 3][row] = a.w;
        }
        {
            int krow = tid >> 4;
            int c4   = tid & 15;
            *(float4*)&Bs[krow][c4 * 4] =
                *(const float4*)(W + (size_t)(k0 + krow) * QKVN + n0 + c4 * 4);
        }
        __syncthreads();

        #pragma unroll
        for (int k = 0; k < GBK; ++k) {
            float4 a0 = *(const float4*)&As[k][ty * 8];
            float4 a1 = *(const float4*)&As[k][ty * 8 + 4];
            float4 bb = *(const float4*)&Bs[k][tx * 4];
            float ar[8] = {a0.x, a0.y, a0.z, a0.w, a1.x, a1.y, a1.z, a1.w};
            float bc[4] = {bb.x, bb.y, bb.z, bb.w};
            #pragma unroll
            for (int r = 0; r < 8; ++r)
                #pragma unroll
                for (int c = 0; c < 4; ++c)
                    acc[r][c] = fmaf(ar[r], bc[c], acc[r][c]);
        }
        __syncthreads();
    }

    const int cg = n0 + tx * 4;
    const int t  = cg / CDIM;
    const int rem = cg - t * CDIM;
    const int h  = rem >> 5;
    const int d  = rem & 31;
    float* dstbase = (t == 0) ? g_q : (t == 1) ? g_k : g_v;
    const float sc = (t == 0) ? SCALE : 1.0f;
    float4 bq = *(const float4*)(bqkv + cg);

    #pragma unroll
    for (int r = 0; r < 8; ++r) {
        int m  = m0 + ty * 8 + r;
        int bw = m / NTOK;
        int nn = m - bw * NTOK;
        float4 val;
        val.x = (acc[r][0] + bq.x) * sc;
        val.y = (acc[r][1] + bq.y) * sc;
        val.z = (acc[r][2] + bq.z) * sc;
        val.w = (acc[r][3] + bq.w) * sc;
        *(float4*)&dstbase[(size_t)((bw * HEADS + h) * NTOK + nn) * DH + d] = val;
    }
}

// ---------------------------------------------------------------------------
// K2: fused attention, TWO heads per block. 288 threads = 9 full warps.
// Dynamic smem layout (floats):
//   K(lh)  at lh*4616            (4608 data + 8 pad)
//   V(lh)  at 9232 + lh*4616
//   BM(lh) at 18464 + lh*2448    (144 x 17)
// total = 23360 floats = 93440 bytes
// ---------------------------------------------------------------------------
#define KVSTR   4616
#define BMOFF   18464
#define BMSTR   2448
#define ATTN_SMEM (23360 * 4)

__global__ __launch_bounds__(288)
void attn2_kernel(const float* __restrict__ mask) {
    extern __shared__ float sm[];

    const int pair = blockIdx.x;          // bw*3 + c
    const int bw   = pair / 3;
    const int c    = pair - bw * 3;
    const int b    = bw / NW;
    const int head0 = bw * HEADS + c * 2; // heads head0, head0+1 (contiguous)
    const int t    = threadIdx.x;         // 0..287
    const int lh   = t / NTOK;            // 0 or 1
    const int row  = t - lh * NTOK;       // 0..143  (every thread owns a row)

    const float4* kb = (const float4*)(g_k + (size_t)head0 * NTOK * DH);
    const float4* vb = (const float4*)(g_v + (size_t)head0 * NTOK * DH);
    const float*  qb = g_q + (size_t)(head0 + lh) * NTOK * DH + row * DH;
    const int wh0   = head0 % (NW * HEADS);
    const float* maskB = mask + (size_t)b * NN2;

    // cooperative K/V load: 2 heads contiguous, 2304 float4 each array
    for (int idx = t; idx < 2 * NTOK * DH / 4; idx += 288) {
        int hh  = idx >= 1152;
        int off = idx - hh * 1152;
        ((float4*)(sm + hh * KVSTR))[off]        = kb[idx];
        ((float4*)(sm + 2 * KVSTR + hh * KVSTR))[off] = vb[idx];
    }

    // per-thread q row
    float q[DH];
    {
        const float4* qr = (const float4*)qb;
        #pragma unroll
        for (int d4 = 0; d4 < 8; ++d4) {
            float4 v4 = qr[d4];
            q[d4 * 4 + 0] = v4.x; q[d4 * 4 + 1] = v4.y;
            q[d4 * 4 + 2] = v4.z; q[d4 * 4 + 3] = v4.w;
        }
    }

    const float* smK  = sm + lh * KVSTR;
    const float* smV  = sm + 2 * KVSTR + lh * KVSTR;
    const float* smBM = sm + BMOFF + lh * BMSTR;

    float o[DH];
    #pragma unroll
    for (int d = 0; d < DH; ++d) o[d] = 0.f;
    float mrun = -CUDART_INF_F;
    float srun = 0.f;

    for (int jt = 0; jt < 9; ++jt) {       // 9 tiles of 16 keys
        __syncthreads();                   // also covers initial K/V load
        // stage bias+mask tiles for both heads: 2 x 576 float4
        for (int idx = t; idx < 1152; idx += 288) {
            int lh2 = idx >= 576;
            int rem = idx - lh2 * 576;
            int r2  = rem >> 2;
            int c4  = rem & 3;
            int gi  = r2 * NTOK + jt * 16 + c4 * 4;
            const float* biasP = g_bias + (size_t)(wh0 + lh2) * NN2;
            float4 bb = *(const float4*)(biasP + gi);
            float4 mm = *(const float4*)(maskB + gi);
            float* dst = sm + BMOFF + lh2 * BMSTR + r2 * 17 + c4 * 4;
            dst[0] = bb.x + mm.x; dst[1] = bb.y + mm.y;
            dst[2] = bb.z + mm.z; dst[3] = bb.w + mm.w;
        }
        __syncthreads();

        float st[16];
        float tmax = -CUDART_INF_F;
        #pragma unroll
        for (int jj = 0; jj < 16; ++jj) {
            const int j = jt * 16 + jj;
            const float4* kr = (const float4*)(smK + j * DH);
            float a0 = 0.f, a1 = 0.f, a2 = 0.f, a3 = 0.f;
            #pragma unroll
            for (int d4 = 0; d4 < 8; ++d4) {
                float4 kv = kr[d4];                  // half-warp broadcast LDS
                a0 = fmaf(q[d4 * 4 + 0], kv.x, a0);
                a1 = fmaf(q[d4 * 4 + 1], kv.y, a1);
                a2 = fmaf(q[d4 * 4 + 2], kv.z, a2);
                a3 = fmaf(q[d4 * 4 + 3], kv.w, a3);
            }
            st[jj] = (a0 + a1) + (a2 + a3) + smBM[row * 17 + jj];
            tmax = fmaxf(tmax, st[jj]);
        }
        const float mnew = fmaxf(mrun, tmax);
        const float corr = __expf(mrun - mnew);      // 0 on first tile
        srun *= corr;
        #pragma unroll
        for (int d = 0; d < DH; ++d) o[d] *= corr;
        #pragma unroll
        for (int jj = 0; jj < 16; ++jj) {
            const float p = __expf(st[jj] - mnew);
            srun += p;
            const float4* vr = (const float4*)(smV + (jt * 16 + jj) * DH);
            #pragma unroll
            for (int d4 = 0; d4 < 8; ++d4) {
                float4 vv = vr[d4];
                o[d4 * 4 + 0] = fmaf(p, vv.x, o[d4 * 4 + 0]);
                o[d4 * 4 + 1] = fmaf(p, vv.y, o[d4 * 4 + 1]);
                o[d4 * 4 + 2] = fmaf(p, vv.z, o[d4 * 4 + 2]);
                o[d4 * 4 + 3] = fmaf(p, vv.w, o[d4 * 4 + 3]);
            }
        }
        mrun = mnew;
    }

    {
        const float inv = 1.0f / srun;
        float* op = g_att + ((size_t)bw * NTOK + row) * CDIM + (c * 2 + lh) * DH;
        #pragma unroll
        for (int d4 = 0; d4 < 8; ++d4) {
            float4 v4;
            v4.x = o[d4 * 4 + 0] * inv; v4.y = o[d4 * 4 + 1] * inv;
            v4.z = o[d4 * 4 + 2] * inv; v4.w = o[d4 * 4 + 3] * inv;
            *(float4*)(op + d4 * 4) = v4;
        }
    }
}

// ---------------------------------------------------------------------------
// K3: projection GEMM (R7 FFMA2 version, measured 237us)
// ---------------------------------------------------------------------------
__global__ __launch_bounds__(256)
void proj_gemm_kernel(const float* __restrict__ Wp,
                      const float* __restrict__ bp,
                      float* __restrict__ out) {
    __shared__ float As[GBK][GBM];
    __shared__ float Bs[GBK][GBN];

    const int m0 = blockIdx.x * GBM;
    const int n0 = blockIdx.y * GBN;
    const int tid = threadIdx.x;
    const int tx = tid & 15;
    const int ty = tid >> 4;

    unsigned long long cp[4][4];
    #pragma unroll
    for (int i = 0; i < 4; ++i)
        #pragma unroll
        for (int j = 0; j < 4; ++j) cp[i][j] = 0ull;

    for (int k0 = 0; k0 < CDIM; k0 += GBK) {
        #pragma unroll
        for (int l = 0; l < 2; ++l) {
            int idx = tid + l * 256;
            int row = idx >> 2;
            int c4  = idx & 3;
            float4 a = *(const float4*)(g_att + (size_t)(m0 + row) * CDIM + k0 + c4 * 4);
            As[c4 * 4 + 0][row] = a.x;
            As[c4 * 4 + 1][row] = a.y;
            As[c4 * 4 + 2][row] = a.z;
            As[c4 * 4 + 3][row] = a.w;
        }
        {
            int krow = tid >> 4;
            int c4   = tid & 15;
            *(float4*)&Bs[krow][c4 * 4] =
                *(const float4*)(Wp + (size_t)(k0 + krow) * CDIM + n0 + c4 * 4);
        }
        __syncthreads();

        #pragma unroll
        for (int k = 0; k < GBK; ++k) {
            const double2* ap = (const double2*)&As[k][ty * 8];
            double2 a01 = ap[0], a23 = ap[1];
            unsigned long long apair[4] = {
                d_as_ull(a01.x), d_as_ull(a01.y),
                d_as_ull(a23.x), d_as_ull(a23.y)};
            float4 bb = *(const float4*)&Bs[k][tx * 4];
            unsigned long long br[4] = {
                pack2(bb.x, bb.x), pack2(bb.y, bb.y),
                pack2(bb.z, bb.z), pack2(bb.w, bb.w)};
            #pragma unroll
            for (int i = 0; i < 4; ++i)
                #pragma unroll
                for (int j = 0; j < 4; ++j)
                    cp[i][j] = fma2(apair[i], br[j], cp[i][j]);
        }
        __syncthreads();
    }

    const int cg = n0 + tx * 4;
    float4 bq = *(const float4*)(bp + cg);
    #pragma unroll
    for (int i = 0; i < 4; ++i) {
        float2 f0 = unpack2(cp[i][0]);
        float2 f1 = unpack2(cp[i][1]);
        float2 f2 = unpack2(cp[i][2]);
        float2 f3 = unpack2(cp[i][3]);
        #pragma unroll
        for (int half = 0; half < 2; ++half) {
            int m = m0 + ty * 8 + 2 * i + half;
            float4 val;
            val.x = (half ? f0.y : f0.x) + bq.x;
            val.y = (half ? f1.y : f1.x) + bq.y;
            val.z = (half ? f2.y : f2.x) + bq.z;
            val.w = (half ? f3.y : f3.x) + bq.w;
            *(float4*)(out + (size_t)m * CDIM + cg) = val;
        }
    }
}

// ---------------------------------------------------------------------------
extern "C" void kernel_launch(void* const* d_in, const int* in_sizes, int n_in,
                              void* d_out, int out_size) {
    const float* x          = (const float*)d_in[0];
    const float* mask       = (const float*)d_in[1];
    const float* w_qkv      = (const float*)d_in[2];
    const float* b_qkv      = (const float*)d_in[3];
    const float* w_proj     = (const float*)d_in[4];
    const float* b_proj     = (const float*)d_in[5];
    const float* bias_table = (const float*)d_in[6];
    const int*   pidx       = (const int*)d_in[7];
    float* out = (float*)d_out;

    cudaFuncSetAttribute(attn2_kernel,
                         cudaFuncAttributeMaxDynamicSharedMemorySize, ATTN_SMEM);

    build_bias_kernel<<<(BIASTOT + 255) / 256, 256>>>(bias_table, pidx);
    qkv_gemm_kernel<<<dim3(MTOT / GBM, QKVN / GBN), 256>>>(x, w_qkv, b_qkv);
    attn2_kernel<<<NHEADTOT / 2, 288, ATTN_SMEM>>>(mask);
    proj_gemm_kernel<<<dim3(MTOT / GBM, CDIM / GBN), 256>>>(w_proj, b_proj, out);
}

// round 11
// speedup vs baseline: 1.6141x; 1.1158x over previous
#include <cuda_runtime.h>
#include <cuda_bf16.h>
#include <math_constants.h>
#include <stdint.h>

// Problem constants
#define BATCH   96
#define NW      10
#define NTOK    144            // window tokens
#define CDIM    192
#define HEADS   6
#define DH      32
#define MTOT    (BATCH*NW*NTOK)        // 138240
#define NHEADTOT (BATCH*NW*HEADS)      // 5760
#define NN2     (NTOK*NTOK)            // 20736
#define BIASTOT (NW*HEADS*NN2)         // 1244160
#define QKVN    (3*CDIM)               // 576
#define SCALE   0.17677669529663687f   // 32^-0.5

// ---------------- packed f32x2 helpers (for proj kernel) -------------------
__device__ __forceinline__ unsigned long long pack2(float lo, float hi) {
    unsigned long long r;
    asm("mov.b64 %0, {%1, %2};" : "=l"(r) : "f"(lo), "f"(hi));
    return r;
}
__device__ __forceinline__ float2 unpack2(unsigned long long v) {
    float2 f;
    asm("mov.b64 {%0, %1}, %2;" : "=f"(f.x), "=f"(f.y) : "l"(v));
    return f;
}
__device__ __forceinline__ unsigned long long fma2(unsigned long long a,
                                                   unsigned long long b,
                                                   unsigned long long c) {
    unsigned long long d;
    asm("fma.rn.f32x2 %0, %1, %2, %3;" : "=l"(d) : "l"(a), "l"(b), "l"(c));
    return d;
}
__device__ __forceinline__ unsigned long long d_as_ull(double x) {
    return __double_as_longlong(x);
}

// -------- scratch (device globals; no runtime allocation allowed) ----------
__device__ float g_q[NHEADTOT * NTOK * DH];   // [head][n][d], pre-scaled
__device__ float g_k[NHEADTOT * NTOK * DH];
__device__ float g_v[NHEADTOT * NTOK * DH];
__device__ float g_att[MTOT * CDIM];          // attention output, [B,nW,N,C]
__device__ float g_bias[BIASTOT];             // [w][h][i*N+j]

// ---------------------------------------------------------------------------
// K0: materialize relative-position bias
// ---------------------------------------------------------------------------
__global__ void build_bias_kernel(const float* __restrict__ bias_table,
                                  const int* __restrict__ pidx) {
    int idx = blockIdx.x * blockDim.x + threadIdx.x;
    if (idx >= BIASTOT) return;
    int wh = idx / NN2;
    int ij = idx - wh * NN2;
    g_bias[idx] = bias_table[pidx[ij] * (NW * HEADS) + wh];
}

// ---------------------------------------------------------------------------
// K1: QKV GEMM (R1 verbatim, at fp32 roofline)
// ---------------------------------------------------------------------------
#define GBM 128
#define GBN 64
#define GBK 16

__global__ __launch_bounds__(256)
void qkv_gemm_kernel(const float* __restrict__ X,
                     const float* __restrict__ W,
                     const float* __restrict__ bqkv) {
    __shared__ float As[GBK][GBM];
    __shared__ float Bs[GBK][GBN];

    const int m0 = blockIdx.x * GBM;
    const int n0 = blockIdx.y * GBN;
    const int tid = threadIdx.x;
    const int tx = tid & 15;
    const int ty = tid >> 4;

    float acc[8][4];
    #pragma unroll
    for (int r = 0; r < 8; ++r)
        #pragma unroll
        for (int c = 0; c < 4; ++c) acc[r][c] = 0.f;

    for (int k0 = 0; k0 < CDIM; k0 += GBK) {
        #pragma unroll
        for (int l = 0; l < 2; ++l) {
            int idx = tid + l * 256;
            int row = idx >> 2;
            int c4  = idx & 3;
            float4 a = *(const float4*)(X + (size_t)(m0 + row) * CDIM + k0 + c4 * 4);
            As[c4 * 4 + 0][row] = a.x;
            As[c4 * 4 + 1][row] = a.y;
            As[c4 * 4 + 2][row] = a.z;
            As[c4 * 4 + 3][row] = a.w;
        }
        {
            int krow = tid >> 4;
            int c4   = tid & 15;
            *(float4*)&Bs[krow][c4 * 4] =
                *(const float4*)(W + (size_t)(k0 + krow) * QKVN + n0 + c4 * 4);
        }
        __syncthreads();

        #pragma unroll
        for (int k = 0; k < GBK; ++k) {
            float4 a0 = *(const float4*)&As[k][ty * 8];
            float4 a1 = *(const float4*)&As[k][ty * 8 + 4];
            float4 bb = *(const float4*)&Bs[k][tx * 4];
            float ar[8] = {a0.x, a0.y, a0.z, a0.w, a1.x, a1.y, a1.z, a1.w};
            float bc[4] = {bb.x, bb.y, bb.z, bb.w};
            #pragma unroll
            for (int r = 0; r < 8; ++r)
                #pragma unroll
                for (int c = 0; c < 4; ++c)
                    acc[r][c] = fmaf(ar[r], bc[c], acc[r][c]);
        }
        __syncthreads();
    }

    const int cg = n0 + tx * 4;
    const int t  = cg / CDIM;
    const int rem = cg - t * CDIM;
    const int h  = rem >> 5;
    const int d  = rem & 31;
    float* dstbase = (t == 0) ? g_q : (t == 1) ? g_k : g_v;
    const float sc = (t == 0) ? SCALE : 1.0f;
    float4 bq = *(const float4*)(bqkv + cg);

    #pragma unroll
    for (int r = 0; r < 8; ++r) {
        int m  = m0 + ty * 8 + r;
        int bw = m / NTOK;
        int nn = m - bw * NTOK;
        float4 val;
        val.x = (acc[r][0] + bq.x) * sc;
        val.y = (acc[r][1] + bq.y) * sc;
        val.z = (acc[r][2] + bq.z) * sc;
        val.w = (acc[r][3] + bq.w) * sc;
        *(float4*)&dstbase[(size_t)((bw * HEADS + h) * NTOK + nn) * DH + d] = val;
    }
}

// ---------------------------------------------------------------------------
// K2: fused attention v3 — one head/block, 160 threads, K/V in smem,
// bias+mask read directly per-thread via LDG (no staging, ONE barrier).
// ---------------------------------------------------------------------------
__global__ __launch_bounds__(160)
void attn_kernel(const float* __restrict__ mask) {
    __shared__ float Ks[NTOK * DH];        // 18432 B
    __shared__ float Vs[NTOK * DH];        // 18432 B

    const int head = blockIdx.x;           // = b*60 + w*6 + h
    const int h    = head % HEADS;
    const int bw   = head / HEADS;
    const int b    = head / (NW * HEADS);
    const int t    = threadIdx.x;

    const float* kb = g_k + (size_t)head * NTOK * DH;
    const float* vb = g_v + (size_t)head * NTOK * DH;
    const float* qb = g_q + (size_t)head * NTOK * DH;

    // cooperative K/V load (coalesced float4)
    for (int idx = t; idx < NTOK * DH / 4; idx += 160) {
        ((float4*)Ks)[idx] = ((const float4*)kb)[idx];
        ((float4*)Vs)[idx] = ((const float4*)vb)[idx];
    }
    __syncthreads();
    if (t >= NTOK) return;                 // idle lanes done after the load

    // per-thread row pointers for bias and mask (sequential 64B per tile)
    const float4* biasR = (const float4*)(g_bias + (size_t)(head % (NW * HEADS)) * NN2
                                          + (size_t)t * NTOK);
    const float4* maskR = (const float4*)(mask + (size_t)b * NN2 + (size_t)t * NTOK);

    // per-thread q row
    float q[DH];
    {
        const float4* qr = (const float4*)(qb + t * DH);
        #pragma unroll
        for (int d4 = 0; d4 < 8; ++d4) {
            float4 v4 = qr[d4];
            q[d4 * 4 + 0] = v4.x; q[d4 * 4 + 1] = v4.y;
            q[d4 * 4 + 2] = v4.z; q[d4 * 4 + 3] = v4.w;
        }
    }

    float o[DH];
    #pragma unroll
    for (int d = 0; d < DH; ++d) o[d] = 0.f;
    float mrun = -CUDART_INF_F;
    float srun = 0.f;

    for (int jt = 0; jt < 9; ++jt) {       // 9 tiles of 16 keys
        // issue bias+mask loads first (latency overlaps the 512 FMAs below)
        float st[16];
        #pragma unroll
        for (int i = 0; i < 4; ++i) {
            float4 bb = biasR[jt * 4 + i];
            float4 mm = maskR[jt * 4 + i];
            st[i * 4 + 0] = bb.x + mm.x;
            st[i * 4 + 1] = bb.y + mm.y;
            st[i * 4 + 2] = bb.z + mm.z;
            st[i * 4 + 3] = bb.w + mm.w;
        }

        float tmax = -CUDART_INF_F;
        #pragma unroll
        for (int jj = 0; jj < 16; ++jj) {
            const int j = jt * 16 + jj;
            const float4* kr = (const float4*)(Ks + j * DH);
            float a0 = 0.f, a1 = 0.f, a2 = 0.f, a3 = 0.f;
            #pragma unroll
            for (int d4 = 0; d4 < 8; ++d4) {
                float4 kv = kr[d4];                  // broadcast LDS
                a0 = fmaf(q[d4 * 4 + 0], kv.x, a0);
                a1 = fmaf(q[d4 * 4 + 1], kv.y, a1);
                a2 = fmaf(q[d4 * 4 + 2], kv.z, a2);
                a3 = fmaf(q[d4 * 4 + 3], kv.w, a3);
            }
            st[jj] += (a0 + a1) + (a2 + a3);
            tmax = fmaxf(tmax, st[jj]);
        }
        const float mnew = fmaxf(mrun, tmax);
        const float corr = __expf(mrun - mnew);      // 0 on first tile
        srun *= corr;
        #pragma unroll
        for (int d = 0; d < DH; ++d) o[d] *= corr;
        #pragma unroll
        for (int jj = 0; jj < 16; ++jj) {
            const float p = __expf(st[jj] - mnew);
            srun += p;
            const float4* vr = (const float4*)(Vs + (jt * 16 + jj) * DH);
            #pragma unroll
            for (int d4 = 0; d4 < 8; ++d4) {
                float4 vv = vr[d4];                  // broadcast LDS
                o[d4 * 4 + 0] = fmaf(p, vv.x, o[d4 * 4 + 0]);
                o[d4 * 4 + 1] = fmaf(p, vv.y, o[d4 * 4 + 1]);
                o[d4 * 4 + 2] = fmaf(p, vv.z, o[d4 * 4 + 2]);
                o[d4 * 4 + 3] = fmaf(p, vv.w, o[d4 * 4 + 3]);
            }
        }
        mrun = mnew;
    }

    {
        const float inv = 1.0f / srun;
        float* op = g_att + ((size_t)bw * NTOK + t) * CDIM + h * DH;
        #pragma unroll
        for (int d4 = 0; d4 < 8; ++d4) {
            float4 v4;
            v4.x = o[d4 * 4 + 0] * inv; v4.y = o[d4 * 4 + 1] * inv;
            v4.z = o[d4 * 4 + 2] * inv; v4.w = o[d4 * 4 + 3] * inv;
            *(float4*)(op + d4 * 4) = v4;
        }
    }
}

// ---------------------------------------------------------------------------
// K3: projection GEMM (R7 FFMA2 version, measured 235us)
// ---------------------------------------------------------------------------
__global__ __launch_bounds__(256)
void proj_gemm_kernel(const float* __restrict__ Wp,
                      const float* __restrict__ bp,
                      float* __restrict__ out) {
    __shared__ float As[GBK][GBM];
    __shared__ float Bs[GBK][GBN];

    const int m0 = blockIdx.x * GBM;
    const int n0 = blockIdx.y * GBN;
    const int tid = threadIdx.x;
    const int tx = tid & 15;
    const int ty = tid >> 4;

    unsigned long long cp[4][4];
    #pragma unroll
    for (int i = 0; i < 4; ++i)
        #pragma unroll
        for (int j = 0; j < 4; ++j) cp[i][j] = 0ull;

    for (int k0 = 0; k0 < CDIM; k0 += GBK) {
        #pragma unroll
        for (int l = 0; l < 2; ++l) {
            int idx = tid + l * 256;
            int row = idx >> 2;
            int c4  = idx & 3;
            float4 a = *(const float4*)(g_att + (size_t)(m0 + row) * CDIM + k0 + c4 * 4);
            As[c4 * 4 + 0][row] = a.x;
            As[c4 * 4 + 1][row] = a.y;
            As[c4 * 4 + 2][row] = a.z;
            As[c4 * 4 + 3][row] = a.w;
        }
        {
            int krow = tid >> 4;
            int c4   = tid & 15;
            *(float4*)&Bs[krow][c4 * 4] =
                *(const float4*)(Wp + (size_t)(k0 + krow) * CDIM + n0 + c4 * 4);
        }
        __syncthreads();

        #pragma unroll
        for (int k = 0; k < GBK; ++k) {
            const double2* ap = (const double2*)&As[k][ty * 8];
            double2 a01 = ap[0], a23 = ap[1];
            unsigned long long apair[4] = {
                d_as_ull(a01.x), d_as_ull(a01.y),
                d_as_ull(a23.x), d_as_ull(a23.y)};
            float4 bb = *(const float4*)&Bs[k][tx * 4];
            unsigned long long br[4] = {
                pack2(bb.x, bb.x), pack2(bb.y, bb.y),
                pack2(bb.z, bb.z), pack2(bb.w, bb.w)};
            #pragma unroll
            for (int i = 0; i < 4; ++i)
                #pragma unroll
                for (int j = 0; j < 4; ++j)
                    cp[i][j] = fma2(apair[i], br[j], cp[i][j]);
        }
        __syncthreads();
    }

    const int cg = n0 + tx * 4;
    float4 bq = *(const float4*)(bp + cg);
    #pragma unroll
    for (int i = 0; i < 4; ++i) {
        float2 f0 = unpack2(cp[i][0]);
        float2 f1 = unpack2(cp[i][1]);
        float2 f2 = unpack2(cp[i][2]);
        float2 f3 = unpack2(cp[i][3]);
        #pragma unroll
        for (int half = 0; half < 2; ++half) {
            int m = m0 + ty * 8 + 2 * i + half;
            float4 val;
            val.x = (half ? f0.y : f0.x) + bq.x;
            val.y = (half ? f1.y : f1.x) + bq.y;
            val.z = (half ? f2.y : f2.x) + bq.z;
            val.w = (half ? f3.y : f3.x) + bq.w;
            *(float4*)(out + (size_t)m * CDIM + cg) = val;
        }
    }
}

// ---------------------------------------------------------------------------
extern "C" void kernel_launch(void* const* d_in, const int* in_sizes, int n_in,
                              void* d_out, int out_size) {
    const float* x          = (const float*)d_in[0];
    const float* mask       = (const float*)d_in[1];
    const float* w_qkv      = (const float*)d_in[2];
    const float* b_qkv      = (const float*)d_in[3];
    const float* w_proj     = (const float*)d_in[4];
    const float* b_proj     = (const float*)d_in[5];
    const float* bias_table = (const float*)d_in[6];
    const int*   pidx       = (const int*)d_in[7];
    float* out = (float*)d_out;

    build_bias_kernel<<<(BIASTOT + 255) / 256, 256>>>(bias_table, pidx);
    qkv_gemm_kernel<<<dim3(MTOT / GBM, QKVN / GBN), 256>>>(x, w_qkv, b_qkv);
    attn_kernel<<<NHEADTOT, 160>>>(mask);
    proj_gemm_kernel<<<dim3(MTOT / GBM, CDIM / GBN), 256>>>(w_proj, b_proj, out);
}

// round 14
// speedup vs baseline: 1.7329x; 1.0736x over previous
#include <cuda_runtime.h>
#include <cuda_bf16.h>
#include <math_constants.h>
#include <stdint.h>

// Problem constants
#define BATCH   96
#define NW      10
#define NTOK    144            // window tokens
#define CDIM    192
#define HEADS   6
#define DH      32
#define MTOT    (BATCH*NW*NTOK)        // 138240
#define NHEADTOT (BATCH*NW*HEADS)      // 5760
#define NN2     (NTOK*NTOK)            // 20736
#define BIASTOT (NW*HEADS*NN2)         // 1244160
#define QKVN    (3*CDIM)               // 576
#define SCALE   0.17677669529663687f   // 32^-0.5

// -------- scratch (device globals; no runtime allocation allowed) ----------
__device__ float g_q[NHEADTOT * NTOK * DH];   // [head][n][d], pre-scaled
__device__ float g_k[NHEADTOT * NTOK * DH];
__device__ float g_v[NHEADTOT * NTOK * DH];
__device__ float g_att[MTOT * CDIM];          // attention output, [B,nW,N,C]
__device__ float g_bias[BIASTOT];             // [w][h][i*N+j]

// ---------------------------------------------------------------------------
// K0: materialize relative-position bias
// ---------------------------------------------------------------------------
__global__ void build_bias_kernel(const float* __restrict__ bias_table,
                                  const int* __restrict__ pidx) {
    int idx = blockIdx.x * blockDim.x + threadIdx.x;
    if (idx >= BIASTOT) return;
    int wh = idx / NN2;
    int ij = idx - wh * NN2;
    g_bias[idx] = bias_table[pidx[ij] * (NW * HEADS) + wh];
}

// ---------------------------------------------------------------------------
// Wide-N SGEMM: BM=64, BN=192, BK=16, 384 threads, 8x4 microtile.
// Warp layout: tx = (lane&15) + 16*(warp%3)  -> 48 col-groups of 4
//              ty = (lane>>4) + 2*(warp/3)   -> 8 row-groups of 8
// Each warp spans 16 tx x 2 ty  => same LDS broadcast pattern as R1.
// A is read only N/192 times from DRAM (3x for qkv, 1x for proj).
// ---------------------------------------------------------------------------
#define WBM 64
#define WBN 192
#define WBK 16

// ---------------- K1: QKV GEMM + scatter to g_q/g_k/g_v --------------------
__global__ __launch_bounds__(384)
void qkv_gemm2_kernel(const float* __restrict__ X,
                      const float* __restrict__ W,
                      const float* __restrict__ bqkv) {
    __shared__ float As[WBK][WBM];    // 4 KB
    __shared__ float Bs[WBK][WBN];    // 12 KB

    const int tid = threadIdx.x;
    const int w   = tid >> 5;
    const int l   = tid & 31;
    const int tx  = (l & 15) + 16 * (w % 3);   // 0..47
    const int ty  = (l >> 4) + 2 * (w / 3);    // 0..7
    const int m0  = blockIdx.x * WBM;
    const int n0  = blockIdx.y * WBN;

    float acc[8][4];
    #pragma unroll
    for (int r = 0; r < 8; ++r)
        #pragma unroll
        for (int c = 0; c < 4; ++c) acc[r][c] = 0.f;

    for (int k0 = 0; k0 < CDIM; k0 += WBK) {
        // ---- A tile: 64 rows x 16 k = 256 float4 (threads 0..255) ----
        if (tid < 256) {
            int row = tid >> 2;
            int c4  = tid & 3;
            float4 a = *(const float4*)(X + (size_t)(m0 + row) * CDIM + k0 + c4 * 4);
            As[c4 * 4 + 0][row] = a.x;
            As[c4 * 4 + 1][row] = a.y;
            As[c4 * 4 + 2][row] = a.z;
            As[c4 * 4 + 3][row] = a.w;
        }
        // ---- B tile: 16 k x 192 n = 768 float4; 2 per thread ----
        #pragma unroll
        for (int ld = 0; ld < 2; ++ld) {
            int idx  = tid + ld * 384;
            int krow = idx / 48;
            int c4   = idx - krow * 48;
            *(float4*)&Bs[krow][c4 * 4] =
                *(const float4*)(W + (size_t)(k0 + krow) * QKVN + n0 + c4 * 4);
        }
        __syncthreads();

        #pragma unroll
        for (int k = 0; k < WBK; ++k) {
            float4 a0 = *(const float4*)&As[k][ty * 8];
            float4 a1 = *(const float4*)&As[k][ty * 8 + 4];
            float4 bb = *(const float4*)&Bs[k][tx * 4];
            float ar[8] = {a0.x, a0.y, a0.z, a0.w, a1.x, a1.y, a1.z, a1.w};
            float bc[4] = {bb.x, bb.y, bb.z, bb.w};
            #pragma unroll
            for (int r = 0; r < 8; ++r)
                #pragma unroll
                for (int c = 0; c < 4; ++c)
                    acc[r][c] = fmaf(ar[r], bc[c], acc[r][c]);
        }
        __syncthreads();
    }

    // ---- epilogue: bias add + scatter to q/k/v (float4 per row) ----
    const int cg = n0 + tx * 4;            // column (multiple of 4, within one head)
    const int t  = cg / CDIM;              // 0=q,1=k,2=v
    const int rem = cg - t * CDIM;
    const int h  = rem >> 5;
    const int d  = rem & 31;
    float* dstbase = (t == 0) ? g_q : (t == 1) ? g_k : g_v;
    const float sc = (t == 0) ? SCALE : 1.0f;
    float4 bq = *(const float4*)(bqkv + cg);

    #pragma unroll
    for (int r = 0; r < 8; ++r) {
        int m  = m0 + ty * 8 + r;
        int bw = m / NTOK;
        int nn = m - bw * NTOK;
        float4 val;
        val.x = (acc[r][0] + bq.x) * sc;
        val.y = (acc[r][1] + bq.y) * sc;
        val.z = (acc[r][2] + bq.z) * sc;
        val.w = (acc[r][3] + bq.w) * sc;
        *(float4*)&dstbase[(size_t)((bw * HEADS + h) * NTOK + nn) * DH + d] = val;
    }
}

// ---------------- K3: projection GEMM -> d_out (BN=192, A read once) -------
__global__ __launch_bounds__(384)
void proj_gemm2_kernel(const float* __restrict__ Wp,
                       const float* __restrict__ bp,
                       float* __restrict__ out) {
    __shared__ float As[WBK][WBM];
    __shared__ float Bs[WBK][WBN];

    const int tid = threadIdx.x;
    const int w   = tid >> 5;
    const int l   = tid & 31;
    const int tx  = (l & 15) + 16 * (w % 3);
    const int ty  = (l >> 4) + 2 * (w / 3);
    const int m0  = blockIdx.x * WBM;

    float acc[8][4];
    #pragma unroll
    for (int r = 0; r < 8; ++r)
        #pragma unroll
        for (int c = 0; c < 4; ++c) acc[r][c] = 0.f;

    for (int k0 = 0; k0 < CDIM; k0 += WBK) {
        if (tid < 256) {
            int row = tid >> 2;
            int c4  = tid & 3;
            float4 a = *(const float4*)(g_att + (size_t)(m0 + row) * CDIM + k0 + c4 * 4);
            As[c4 * 4 + 0][row] = a.x;
            As[c4 * 4 + 1][row] = a.y;
            As[c4 * 4 + 2][row] = a.z;
            As[c4 * 4 + 3][row] = a.w;
        }
        #pragma unroll
        for (int ld = 0; ld < 2; ++ld) {
            int idx  = tid + ld * 384;
            int krow = idx / 48;
            int c4   = idx - krow * 48;
            *(float4*)&Bs[krow][c4 * 4] =
                *(const float4*)(Wp + (size_t)(k0 + krow) * CDIM + c4 * 4);
        }
        __syncthreads();

        #pragma unroll
        for (int k = 0; k < WBK; ++k) {
            float4 a0 = *(const float4*)&As[k][ty * 8];
            float4 a1 = *(const float4*)&As[k][ty * 8 + 4];
            float4 bb = *(const float4*)&Bs[k][tx * 4];
            float ar[8] = {a0.x, a0.y, a0.z, a0.w, a1.x, a1.y, a1.z, a1.w};
            float bc[4] = {bb.x, bb.y, bb.z, bb.w};
            #pragma unroll
            for (int r = 0; r < 8; ++r)
                #pragma unroll
                for (int c = 0; c < 4; ++c)
                    acc[r][c] = fmaf(ar[r], bc[c], acc[r][c]);
        }
        __syncthreads();
    }

    const int cg = tx * 4;
    float4 bq = *(const float4*)(bp + cg);
    #pragma unroll
    for (int r = 0; r < 8; ++r) {
        int m = m0 + ty * 8 + r;
        float4 val;
        val.x = acc[r][0] + bq.x;
        val.y = acc[r][1] + bq.y;
        val.z = acc[r][2] + bq.z;
        val.w = acc[r][3] + bq.w;
        *(float4*)(out + (size_t)m * CDIM + cg) = val;
    }
}

// ---------------------------------------------------------------------------
// K2: fused attention, one block per (b,w,h) head. (R1 verbatim, 591us)
// ---------------------------------------------------------------------------
__global__ __launch_bounds__(160)
void attn_kernel(const float* __restrict__ mask) {
    __shared__ float Ks[NTOK * DH];        // 18432 B
    __shared__ float Vs[NTOK * DH];        // 18432 B
    __shared__ float BMs[NTOK * 17];       // 9792 B

    const int head = blockIdx.x;           // = b*60 + w*6 + h
    const int h    = head % HEADS;
    const int bw   = head / HEADS;
    const int b    = head / (NW * HEADS);
    const int t    = threadIdx.x;

    const float* kb = g_k + (size_t)head * NTOK * DH;
    const float* vb = g_v + (size_t)head * NTOK * DH;
    const float* qb = g_q + (size_t)head * NTOK * DH;
    const float* biasWH = g_bias + (size_t)(head % (NW * HEADS)) * NN2;
    const float* maskB  = mask + (size_t)b * NN2;

    for (int idx = t; idx < NTOK * DH / 4; idx += 160) {
        ((float4*)Ks)[idx] = ((const float4*)kb)[idx];
        ((float4*)Vs)[idx] = ((const float4*)vb)[idx];
    }

    float q[DH];
    if (t < NTOK) {
        const float4* qr = (const float4*)(qb + t * DH);
        #pragma unroll
        for (int d4 = 0; d4 < 8; ++d4) {
            float4 v4 = qr[d4];
            q[d4 * 4 + 0] = v4.x; q[d4 * 4 + 1] = v4.y;
            q[d4 * 4 + 2] = v4.z; q[d4 * 4 + 3] = v4.w;
        }
    }

    float o[DH];
    #pragma unroll
    for (int d = 0; d < DH; ++d) o[d] = 0.f;
    float mrun = -CUDART_INF_F;
    float srun = 0.f;

    for (int jt = 0; jt < 9; ++jt) {       // 9 tiles of 16 keys
        __syncthreads();                   // also covers initial K/V load
        for (int idx = t; idx < 576; idx += 160) {
            int row = idx >> 2;
            int c4  = idx & 3;
            int gi  = row * NTOK + jt * 16 + c4 * 4;
            float4 bb = *(const float4*)(biasWH + gi);
            float4 mm = *(const float4*)(maskB + gi);
            float* dst = &BMs[row * 17 + c4 * 4];
            dst[0] = bb.x + mm.x; dst[1] = bb.y + mm.y;
            dst[2] = bb.z + mm.z; dst[3] = bb.w + mm.w;
        }
        __syncthreads();

        if (t < NTOK) {
            float st[16];
            float tmax = -CUDART_INF_F;
            #pragma unroll
            for (int jj = 0; jj < 16; ++jj) {
                const int j = jt * 16 + jj;
                const float4* kr = (const float4*)(Ks + j * DH);
                float a0 = 0.f, a1 = 0.f, a2 = 0.f, a3 = 0.f;
                #pragma unroll
                for (int d4 = 0; d4 < 8; ++d4) {
                    float4 kv = kr[d4];                  // broadcast LDS
                    a0 = fmaf(q[d4 * 4 + 0], kv.x, a0);
                    a1 = fmaf(q[d4 * 4 + 1], kv.y, a1);
                    a2 = fmaf(q[d4 * 4 + 2], kv.z, a2);
                    a3 = fmaf(q[d4 * 4 + 3], kv.w, a3);
                }
                st[jj] = (a0 + a1) + (a2 + a3) + BMs[t * 17 + jj];
                tmax = fmaxf(tmax, st[jj]);
            }
            const float mnew = fmaxf(mrun, tmax);
            const float corr = __expf(mrun - mnew);      // 0 on first tile
            srun *= corr;
            #pragma unroll
            for (int d = 0; d < DH; ++d) o[d] *= corr;
            #pragma unroll
            for (int jj = 0; jj < 16; ++jj) {
                const float p = __expf(st[jj] - mnew);
                srun += p;
                const float4* vr = (const float4*)(Vs + (jt * 16 + jj) * DH);
                #pragma unroll
                for (int d4 = 0; d4 < 8; ++d4) {
                    float4 vv = vr[d4];                  // broadcast LDS
                    o[d4 * 4 + 0] = fmaf(p, vv.x, o[d4 * 4 + 0]);
                    o[d4 * 4 + 1] = fmaf(p, vv.y, o[d4 * 4 + 1]);
                    o[d4 * 4 + 2] = fmaf(p, vv.z, o[d4 * 4 + 2]);
                    o[d4 * 4 + 3] = fmaf(p, vv.w, o[d4 * 4 + 3]);
                }
            }
            mrun = mnew;
        }
    }

    if (t < NTOK) {
        const float inv = 1.0f / srun;
        float* op = g_att + ((size_t)bw * NTOK + t) * CDIM + h * DH;
        #pragma unroll
        for (int d4 = 0; d4 < 8; ++d4) {
            float4 v4;
            v4.x = o[d4 * 4 + 0] * inv; v4.y = o[d4 * 4 + 1] * inv;
            v4.z = o[d4 * 4 + 2] * inv; v4.w = o[d4 * 4 + 3] * inv;
            *(float4*)(op + d4 * 4) = v4;
        }
    }
}

// ---------------------------------------------------------------------------
extern "C" void kernel_launch(void* const* d_in, const int* in_sizes, int n_in,
                              void* d_out, int out_size) {
    const float* x          = (const float*)d_in[0];
    const float* mask       = (const float*)d_in[1];
    const float* w_qkv      = (const float*)d_in[2];
    const float* b_qkv      = (const float*)d_in[3];
    const float* w_proj     = (const float*)d_in[4];
    const float* b_proj     = (const float*)d_in[5];
    const float* bias_table = (const float*)d_in[6];
    const int*   pidx       = (const int*)d_in[7];
    float* out = (float*)d_out;

    build_bias_kernel<<<(BIASTOT + 255) / 256, 256>>>(bias_table, pidx);
    qkv_gemm2_kernel<<<dim3(MTOT / WBM, QKVN / WBN), 384>>>(x, w_qkv, b_qkv);
    attn_kernel<<<NHEADTOT, 160>>>(mask);
    proj_gemm2_kernel<<<MTOT / WBM, 384>>>(w_proj, b_proj, out);
}

// round 15
// speedup vs baseline: 1.7767x; 1.0252x over previous
#include <cuda_runtime.h>
#include <cuda_bf16.h>
#include <math_constants.h>
#include <stdint.h>

// Problem constants
#define BATCH   96
#define NW      10
#define NTOK    144            // window tokens
#define CDIM    192
#define HEADS   6
#define DH      32
#define MTOT    (BATCH*NW*NTOK)        // 138240
#define NHEADTOT (BATCH*NW*HEADS)      // 5760
#define NN2     (NTOK*NTOK)            // 20736
#define BIASTOT (NW*HEADS*NN2)         // 1244160
#define QKVN    (3*CDIM)               // 576
#define SCALE   0.17677669529663687f   // 32^-0.5

// ---------------- cp.async helpers (Ampere-baseline PTX) -------------------
__device__ __forceinline__ uint32_t s2u(const void* p) {
    uint32_t a;
    asm("{ .reg .u64 t; cvta.to.shared.u64 t, %1; cvt.u32.u64 %0, t; }"
        : "=r"(a) : "l"(p));
    return a;
}
__device__ __forceinline__ void cp_async16(uint32_t s, const void* g) {
    asm volatile("cp.async.cg.shared.global [%0], [%1], 16;" :: "r"(s), "l"(g));
}
#define CP_COMMIT() asm volatile("cp.async.commit_group;" ::: "memory")
#define CP_WAIT0()  asm volatile("cp.async.wait_group 0;" ::: "memory")

// -------- scratch (device globals; no runtime allocation allowed) ----------
__device__ float g_q[NHEADTOT * NTOK * DH];   // [head][n][d], pre-scaled
__device__ float g_k[NHEADTOT * NTOK * DH];
__device__ float g_v[NHEADTOT * NTOK * DH];
__device__ float g_att[MTOT * CDIM];          // attention output, [B,nW,N,C]
__device__ float g_bias[BIASTOT];             // [w][h][i*N+j]

// ---------------------------------------------------------------------------
// K0: materialize relative-position bias
// ---------------------------------------------------------------------------
__global__ void build_bias_kernel(const float* __restrict__ bias_table,
                                  const int* __restrict__ pidx) {
    int idx = blockIdx.x * blockDim.x + threadIdx.x;
    if (idx >= BIASTOT) return;
    int wh = idx / NN2;
    int ij = idx - wh * NN2;
    g_bias[idx] = bias_table[pidx[ij] * (NW * HEADS) + wh];
}

// ---------------------------------------------------------------------------
// Pipelined wide-N SGEMM: BM=64, BN=192, BK=16, 384 threads, 8x4 microtile.
// Double-buffered smem; B tiles via cp.async (no regs), A tile via 4-reg
// LDG prefetch. ONE __syncthreads per k-iteration; GMEM latency overlapped.
// ---------------------------------------------------------------------------
#define WBM 64
#define WBN 192
#define WBK 16
#define NKT (CDIM / WBK)    // 12

// ---------------- K1: QKV GEMM + scatter to g_q/g_k/g_v --------------------
__global__ __launch_bounds__(384)
void qkv_gemm3_kernel(const float* __restrict__ X,
                      const float* __restrict__ W,
                      const float* __restrict__ bqkv) {
    __shared__ float As[2][WBK][WBM];    // 8 KB
    __shared__ float Bs[2][WBK][WBN];    // 24 KB

    const int tid = threadIdx.x;
    const int w   = tid >> 5;
    const int l   = tid & 31;
    const int tx  = (l & 15) + 16 * (w % 3);   // 0..47
    const int ty  = (l >> 4) + 2 * (w / 3);    // 0..7
    const int m0  = blockIdx.x * WBM;
    const int n0  = blockIdx.y * WBN;

    // B cp.async chunk coords (2 chunks of 16B per thread)
    const int bk0 = tid / 48,         bc0 = tid - bk0 * 48;
    const int bk1 = (tid + 384) / 48, bc1 = (tid + 384) - bk1 * 48;
    const float* bg0 = W + (size_t)bk0 * QKVN + n0 + bc0 * 4;
    const float* bg1 = W + (size_t)bk1 * QKVN + n0 + bc1 * 4;

    // A prefetch coords (threads 0..255, one float4 each)
    const int ar = tid >> 2, ac4 = tid & 3;
    const float* ag = X + (size_t)(m0 + ar) * CDIM + ac4 * 4;

    float acc[8][4];
    #pragma unroll
    for (int r = 0; r < 8; ++r)
        #pragma unroll
        for (int c = 0; c < 4; ++c) acc[r][c] = 0.f;

    float4 areg;

    // ---- prologue: stage tile 0 ----
    if (tid < 256) areg = *(const float4*)ag;
    cp_async16(s2u(&Bs[0][bk0][bc0 * 4]), bg0);
    cp_async16(s2u(&Bs[0][bk1][bc1 * 4]), bg1);
    CP_COMMIT();
    if (tid < 256) {
        As[0][ac4 * 4 + 0][ar] = areg.x;
        As[0][ac4 * 4 + 1][ar] = areg.y;
        As[0][ac4 * 4 + 2][ar] = areg.z;
        As[0][ac4 * 4 + 3][ar] = areg.w;
    }
    CP_WAIT0();
    __syncthreads();

    for (int kt = 0; kt < NKT; ++kt) {
        const int cur = kt & 1;
        const int nxt = cur ^ 1;
        if (kt < NKT - 1) {
            const int k0 = (kt + 1) * WBK;
            if (tid < 256) areg = *(const float4*)(ag + k0);
            cp_async16(s2u(&Bs[nxt][bk0][bc0 * 4]), bg0 + (size_t)k0 * QKVN);
            cp_async16(s2u(&Bs[nxt][bk1][bc1 * 4]), bg1 + (size_t)k0 * QKVN);
            CP_COMMIT();
        }

        #pragma unroll
        for (int k = 0; k < WBK; ++k) {
            float4 a0 = *(const float4*)&As[cur][k][ty * 8];
            float4 a1 = *(const float4*)&As[cur][k][ty * 8 + 4];
            float4 bb = *(const float4*)&Bs[cur][k][tx * 4];
            float arr[8] = {a0.x, a0.y, a0.z, a0.w, a1.x, a1.y, a1.z, a1.w};
            float bc[4]  = {bb.x, bb.y, bb.z, bb.w};
            #pragma unroll
            for (int r = 0; r < 8; ++r)
                #pragma unroll
                for (int c = 0; c < 4; ++c)
                    acc[r][c] = fmaf(arr[r], bc[c], acc[r][c]);
        }

        if (kt < NKT - 1) {
            if (tid < 256) {
                As[nxt][ac4 * 4 + 0][ar] = areg.x;
                As[nxt][ac4 * 4 + 1][ar] = areg.y;
                As[nxt][ac4 * 4 + 2][ar] = areg.z;
                As[nxt][ac4 * 4 + 3][ar] = areg.w;
            }
            CP_WAIT0();
        }
        __syncthreads();
    }

    // ---- epilogue: bias add + scatter to q/k/v (float4 per row) ----
    const int cg = n0 + tx * 4;            // column (multiple of 4, within one head)
    const int t  = cg / CDIM;              // 0=q,1=k,2=v
    const int rem = cg - t * CDIM;
    const int h  = rem >> 5;
    const int d  = rem & 31;
    float* dstbase = (t == 0) ? g_q : (t == 1) ? g_k : g_v;
    const float sc = (t == 0) ? SCALE : 1.0f;
    float4 bq = *(const float4*)(bqkv + cg);

    #pragma unroll
    for (int r = 0; r < 8; ++r) {
        int m  = m0 + ty * 8 + r;
        int bw = m / NTOK;
        int nn = m - bw * NTOK;
        float4 val;
        val.x = (acc[r][0] + bq.x) * sc;
        val.y = (acc[r][1] + bq.y) * sc;
        val.z = (acc[r][2] + bq.z) * sc;
        val.w = (acc[r][3] + bq.w) * sc;
        *(float4*)&dstbase[(size_t)((bw * HEADS + h) * NTOK + nn) * DH + d] = val;
    }
}

// ---------------- K3: projection GEMM -> d_out (pipelined) -----------------
__global__ __launch_bounds__(384)
void proj_gemm3_kernel(const float* __restrict__ Wp,
                       const float* __restrict__ bp,
                       float* __restrict__ out) {
    __shared__ float As[2][WBK][WBM];
    __shared__ float Bs[2][WBK][WBN];

    const int tid = threadIdx.x;
    const int w   = tid >> 5;
    const int l   = tid & 31;
    const int tx  = (l & 15) + 16 * (w % 3);
    const int ty  = (l >> 4) + 2 * (w / 3);
    const int m0  = blockIdx.x * WBM;

    const int bk0 = tid / 48,         bc0 = tid - bk0 * 48;
    const int bk1 = (tid + 384) / 48, bc1 = (tid + 384) - bk1 * 48;
    const float* bg0 = Wp + (size_t)bk0 * CDIM + bc0 * 4;
    const float* bg1 = Wp + (size_t)bk1 * CDIM + bc1 * 4;

    const int ar = tid >> 2, ac4 = tid & 3;
    const float* ag = g_att + (size_t)(m0 + ar) * CDIM + ac4 * 4;

    float acc[8][4];
    #pragma unroll
    for (int r = 0; r < 8; ++r)
        #pragma unroll
        for (int c = 0; c < 4; ++c) acc[r][c] = 0.f;

    float4 areg;

    if (tid < 256) areg = *(const float4*)ag;
    cp_async16(s2u(&Bs[0][bk0][bc0 * 4]), bg0);
    cp_async16(s2u(&Bs[0][bk1][bc1 * 4]), bg1);
    CP_COMMIT();
    if (tid < 256) {
        As[0][ac4 * 4 + 0][ar] = areg.x;
        As[0][ac4 * 4 + 1][ar] = areg.y;
        As[0][ac4 * 4 + 2][ar] = areg.z;
        As[0][ac4 * 4 + 3][ar] = areg.w;
    }
    CP_WAIT0();
    __syncthreads();

    for (int kt = 0; kt < NKT; ++kt) {
        const int cur = kt & 1;
        const int nxt = cur ^ 1;
        if (kt < NKT - 1) {
            const int k0 = (kt + 1) * WBK;
            if (tid < 256) areg = *(const float4*)(ag + k0);
            cp_async16(s2u(&Bs[nxt][bk0][bc0 * 4]), bg0 + (size_t)k0 * CDIM);
            cp_async16(s2u(&Bs[nxt][bk1][bc1 * 4]), bg1 + (size_t)k0 * CDIM);
            CP_COMMIT();
        }

        #pragma unroll
        for (int k = 0; k < WBK; ++k) {
            float4 a0 = *(const float4*)&As[cur][k][ty * 8];
            float4 a1 = *(const float4*)&As[cur][k][ty * 8 + 4];
            float4 bb = *(const float4*)&Bs[cur][k][tx * 4];
            float arr[8] = {a0.x, a0.y, a0.z, a0.w, a1.x, a1.y, a1.z, a1.w};
            float bc[4]  = {bb.x, bb.y, bb.z, bb.w};
            #pragma unroll
            for (int r = 0; r < 8; ++r)
                #pragma unroll
                for (int c = 0; c < 4; ++c)
                    acc[r][c] = fmaf(arr[r], bc[c], acc[r][c]);
        }

        if (kt < NKT - 1) {
            if (tid < 256) {
                As[nxt][ac4 * 4 + 0][ar] = areg.x;
                As[nxt][ac4 * 4 + 1][ar] = areg.y;
                As[nxt][ac4 * 4 + 2][ar] = areg.z;
                As[nxt][ac4 * 4 + 3][ar] = areg.w;
            }
            CP_WAIT0();
        }
        __syncthreads();
    }

    const int cg = tx * 4;
    float4 bq = *(const float4*)(bp + cg);
    #pragma unroll
    for (int r = 0; r < 8; ++r) {
        int m = m0 + ty * 8 + r;
        float4 val;
        val.x = acc[r][0] + bq.x;
        val.y = acc[r][1] + bq.y;
        val.z = acc[r][2] + bq.z;
        val.w = acc[r][3] + bq.w;
        *(float4*)(out + (size_t)m * CDIM + cg) = val;
    }
}

// ---------------------------------------------------------------------------
// K2: fused attention, one block per (b,w,h) head. (R1 verbatim, 591us)
// ---------------------------------------------------------------------------
__global__ __launch_bounds__(160)
void attn_kernel(const float* __restrict__ mask) {
    __shared__ float Ks[NTOK * DH];        // 18432 B
    __shared__ float Vs[NTOK * DH];        // 18432 B
    __shared__ float BMs[NTOK * 17];       // 9792 B

    const int head = blockIdx.x;           // = b*60 + w*6 + h
    const int h    = head % HEADS;
    const int bw   = head / HEADS;
    const int b    = head / (NW * HEADS);
    const int t    = threadIdx.x;

    const float* kb = g_k + (size_t)head * NTOK * DH;
    const float* vb = g_v + (size_t)head * NTOK * DH;
    const float* qb = g_q + (size_t)head * NTOK * DH;
    const float* biasWH = g_bias + (size_t)(head % (NW * HEADS)) * NN2;
    const float* maskB  = mask + (size_t)b * NN2;

    for (int idx = t; idx < NTOK * DH / 4; idx += 160) {
        ((float4*)Ks)[idx] = ((const float4*)kb)[idx];
        ((float4*)Vs)[idx] = ((const float4*)vb)[idx];
    }

    float q[DH];
    if (t < NTOK) {
        const float4* qr = (const float4*)(qb + t * DH);
        #pragma unroll
        for (int d4 = 0; d4 < 8; ++d4) {
            float4 v4 = qr[d4];
            q[d4 * 4 + 0] = v4.x; q[d4 * 4 + 1] = v4.y;
            q[d4 * 4 + 2] = v4.z; q[d4 * 4 + 3] = v4.w;
        }
    }

    float o[DH];
    #pragma unroll
    for (int d = 0; d < DH; ++d) o[d] = 0.f;
    float mrun = -CUDART_INF_F;
    float srun = 0.f;

    for (int jt = 0; jt < 9; ++jt) {       // 9 tiles of 16 keys
        __syncthreads();                   // also covers initial K/V load
        for (int idx = t; idx < 576; idx += 160) {
            int row = idx >> 2;
            int c4  = idx & 3;
            int gi  = row * NTOK + jt * 16 + c4 * 4;
            float4 bb = *(const float4*)(biasWH + gi);
            float4 mm = *(const float4*)(maskB + gi);
            float* dst = &BMs[row * 17 + c4 * 4];
            dst[0] = bb.x + mm.x; dst[1] = bb.y + mm.y;
            dst[2] = bb.z + mm.z; dst[3] = bb.w + mm.w;
        }
        __syncthreads();

        if (t < NTOK) {
            float st[16];
            float tmax = -CUDART_INF_F;
            #pragma unroll
            for (int jj = 0; jj < 16; ++jj) {
                const int j = jt * 16 + jj;
                const float4* kr = (const float4*)(Ks + j * DH);
                float a0 = 0.f, a1 = 0.f, a2 = 0.f, a3 = 0.f;
                #pragma unroll
                for (int d4 = 0; d4 < 8; ++d4) {
                    float4 kv = kr[d4];                  // broadcast LDS
                    a0 = fmaf(q[d4 * 4 + 0], kv.x, a0);
                    a1 = fmaf(q[d4 * 4 + 1], kv.y, a1);
                    a2 = fmaf(q[d4 * 4 + 2], kv.z, a2);
                    a3 = fmaf(q[d4 * 4 + 3], kv.w, a3);
                }
                st[jj] = (a0 + a1) + (a2 + a3) + BMs[t * 17 + jj];
                tmax = fmaxf(tmax, st[jj]);
            }
            const float mnew = fmaxf(mrun, tmax);
            const float corr = __expf(mrun - mnew);      // 0 on first tile
            srun *= corr;
            #pragma unroll
            for (int d = 0; d < DH; ++d) o[d] *= corr;
            #pragma unroll
            for (int jj = 0; jj < 16; ++jj) {
                const float p = __expf(st[jj] - mnew);
                srun += p;
                const float4* vr = (const float4*)(Vs + (jt * 16 + jj) * DH);
                #pragma unroll
                for (int d4 = 0; d4 < 8; ++d4) {
                    float4 vv = vr[d4];                  // broadcast LDS
                    o[d4 * 4 + 0] = fmaf(p, vv.x, o[d4 * 4 + 0]);
                    o[d4 * 4 + 1] = fmaf(p, vv.y, o[d4 * 4 + 1]);
                    o[d4 * 4 + 2] = fmaf(p, vv.z, o[d4 * 4 + 2]);
                    o[d4 * 4 + 3] = fmaf(p, vv.w, o[d4 * 4 + 3]);
                }
            }
            mrun = mnew;
        }
    }

    if (t < NTOK) {
        const float inv = 1.0f / srun;
        float* op = g_att + ((size_t)bw * NTOK + t) * CDIM + h * DH;
        #pragma unroll
        for (int d4 = 0; d4 < 8; ++d4) {
            float4 v4;
            v4.x = o[d4 * 4 + 0] * inv; v4.y = o[d4 * 4 + 1] * inv;
            v4.z = o[d4 * 4 + 2] * inv; v4.w = o[d4 * 4 + 3] * inv;
            *(float4*)(op + d4 * 4) = v4;
        }
    }
}

// ---------------------------------------------------------------------------
extern "C" void kernel_launch(void* const* d_in, const int* in_sizes, int n_in,
                              void* d_out, int out_size) {
    const float* x          = (const float*)d_in[0];
    const float* mask       = (const float*)d_in[1];
    const float* w_qkv      = (const float*)d_in[2];
    const float* b_qkv      = (const float*)d_in[3];
    const float* w_proj     = (const float*)d_in[4];
    const float* b_proj     = (const float*)d_in[5];
    const float* bias_table = (const float*)d_in[6];
    const int*   pidx       = (const int*)d_in[7];
    float* out = (float*)d_out;

    build_bias_kernel<<<(BIASTOT + 255) / 256, 256>>>(bias_table, pidx);
    qkv_gemm3_kernel<<<dim3(MTOT / WBM, QKVN / WBN), 384>>>(x, w_qkv, b_qkv);
    attn_kernel<<<NHEADTOT, 160>>>(mask);
    proj_gemm3_kernel<<<MTOT / WBM, 384>>>(w_proj, b_proj, out);
}